// round 14
// baseline (speedup 1.0000x reference)
#include <cuda_runtime.h>
#include <cstdint>

// Scratch (module-scope device globals; no runtime allocation)
// g_y and g_att are stored in ROLLED coordinates: R(h,w) = natural(h+4, w+4).
__device__ float g_y[576LL * 262144];    // qkv-linear output, [o][b][pos_rolled]
__device__ float g_att[192LL * 262144];  // attention output,  [c][b][pos_rolled]

// ---------------------------------------------------------------------------
__device__ __forceinline__ uint32_t smem_u32(const void* p) {
  uint32_t a;
  asm("{ .reg .u64 t; cvta.to.shared.u64 t, %1; cvt.u32.u64 %0, t; }"
      : "=r"(a) : "l"(p));
  return a;
}
#define CPA16(dst, src, sz) \
  asm volatile("cp.async.cg.shared.global [%0], [%1], 16, %2;" ::"r"(dst), "l"(src), "r"(sz))
#define CPA_COMMIT() asm volatile("cp.async.commit_group;")
#define CPA_WAIT(n) asm volatile("cp.async.wait_group %0;" ::"n"(n) : "memory")

__device__ __forceinline__ uint32_t f2tf(float f) {
  uint32_t u;
  asm("cvt.rna.tf32.f32 %0, %1;" : "=r"(u) : "f"(f));
  return u;
}
__device__ __forceinline__ void mma8(float* d, const uint32_t* a,
                                     const uint32_t* b) {
  asm volatile(
      "mma.sync.aligned.m16n8k8.row.col.f32.tf32.tf32.f32 "
      "{%0,%1,%2,%3},{%4,%5,%6,%7},{%8,%9},{%0,%1,%2,%3};"
      : "+f"(d[0]), "+f"(d[1]), "+f"(d[2]), "+f"(d[3])
      : "r"(a[0]), "r"(a[1]), "r"(a[2]), "r"(a[3]), "r"(b[0]), "r"(b[1]));
}

// ---------------------------------------------------------------------------
// Out[m, (h',w')] = sum_k W[m,k] * In[k, (h,w)] with (h',w') = (h+roll, w+roll)
// mod 256 applied in the epilogue. CTA tile 128x128, K=192 (12 chunks of 16,
// double-buffered cp.async; round-12 structure).
// ---------------------------------------------------------------------------
__global__ void __launch_bounds__(256, 2) gemm_mma(
    const float* __restrict__ W, const float* __restrict__ In,
    float* __restrict__ Out, int Mvalid, long long ch_str, long long b_str,
    long long o_str, long long ob_str, int roll) {
  __shared__ __align__(16) float As[2][128 * 20];
  __shared__ __align__(16) float Bs[2][16 * 136];

  const int tid = threadIdx.x;
  const int warp = tid >> 5, lane = tid & 31, gid = lane >> 2, tig = lane & 3;
  const int wm = warp & 1, wn = warp >> 1;
  const int m0 = blockIdx.y << 7;
  const int n0 = blockIdx.x << 7;
  const int bb = n0 >> 16, pos0 = n0 & 65535;
  const int h = pos0 >> 8, w0 = pos0 & 255;
  const float* inb = In + bb * b_str + pos0;
  const uint32_t sA = smem_u32(As), sB = smem_u32(Bs);

  float acc[4][4][4];
#pragma unroll
  for (int i = 0; i < 4; ++i)
#pragma unroll
    for (int j = 0; j < 4; ++j)
#pragma unroll
      for (int q = 0; q < 4; ++q) acc[i][j][q] = 0.f;

  auto loadA = [&](int buf, int kc) {
#pragma unroll
    for (int t = 0; t < 2; ++t) {
      int idx = (t << 8) + tid;
      int r = idx >> 2, q = idx & 3;
      int m = m0 + r;
      int valid = m < Mvalid;
      const float* src = W + (long long)(valid ? m : 0) * 192 + kc + (q << 2);
      uint32_t dst = sA + (uint32_t)(buf * 2560 + r * 20 + q * 4) * 4;
      CPA16(dst, src, valid ? 16 : 0);
    }
  };
  auto loadB = [&](int buf, int kc) {
#pragma unroll
    for (int t = 0; t < 2; ++t) {
      int idx = (t << 8) + tid;
      int r = idx >> 5, q = idx & 31;
      const float* src = inb + (long long)(kc + r) * ch_str + (q << 2);
      uint32_t dst = sB + (uint32_t)(buf * 2176 + r * 136 + q * 4) * 4;
      CPA16(dst, src, 16);
    }
  };

  auto compute = [&](int buf) {
    const float* A = As[buf];
    const float* B = Bs[buf];
#pragma unroll
    for (int kb = 0; kb < 2; ++kb) {
      const int kk = kb * 8;
      uint32_t af[4][4];
#pragma unroll
      for (int mf = 0; mf < 4; ++mf) {
        const float* ap = A + (wm * 64 + mf * 16 + gid) * 20 + kk + tig;
        af[mf][0] = f2tf(ap[0]);
        af[mf][1] = f2tf(ap[160]);
        af[mf][2] = f2tf(ap[4]);
        af[mf][3] = f2tf(ap[164]);
      }
      uint32_t bf[4][2];
#pragma unroll
      for (int nf = 0; nf < 4; ++nf) {
        const float* bp = B + (kk + tig) * 136 + wn * 32 + nf * 8 + gid;
        bf[nf][0] = f2tf(bp[0]);
        bf[nf][1] = f2tf(bp[544]);
      }
#pragma unroll
      for (int mf = 0; mf < 4; ++mf)
#pragma unroll
        for (int nf = 0; nf < 4; ++nf) mma8(acc[mf][nf], af[mf], bf[nf]);
    }
  };

  loadA(0, 0);
  loadB(0, 0);
  CPA_COMMIT();
#pragma unroll 1
  for (int i = 0; i < 12; ++i) {
    if (i + 1 < 12) {
      loadA((i + 1) & 1, (i + 1) * 16);
      loadB((i + 1) & 1, (i + 1) * 16);
      CPA_COMMIT();
      CPA_WAIT(1);
    } else {
      CPA_WAIT(0);
    }
    __syncthreads();
    compute(i & 1);
    __syncthreads();
  }

  // Epilogue: float2 stores with (h,w) roll. Shift is even -> a float2 never
  // straddles the wrap; only its base address changes.
  const int hp = (h + roll) & 255;
  const long long rowbase = bb * ob_str + ((long long)hp << 8);
#pragma unroll
  for (int mf = 0; mf < 4; ++mf) {
    int mA = m0 + wm * 64 + mf * 16 + gid;
    int mB = mA + 8;
#pragma unroll
    for (int nf = 0; nf < 4; ++nf) {
      int w = w0 + wn * 32 + nf * 8 + 2 * tig;
      int wp = (w + roll) & 255;
      if (mA < Mvalid)
        *(float2*)(Out + (long long)mA * o_str + rowbase + wp) =
            make_float2(acc[mf][nf][0], acc[mf][nf][1]);
      if (mB < Mvalid)
        *(float2*)(Out + (long long)mB * o_str + rowbase + wp) =
            make_float2(acc[mf][nf][2], acc[mf][nf][3]);
    }
  }
}

// ---------------------------------------------------------------------------
// k2: per (window, head). g_y / g_att are in rolled coords, so windows are
// 32B-aligned and branch-free. Gather into registers, depthwise 3x3 via warp
// shuffles, L2-norm channel attention (2x2 blocking), aligned scatter.
// ---------------------------------------------------------------------------
__global__ void __launch_bounds__(256) k2_dw_attn(
    const float* __restrict__ dw_w, const float* __restrict__ temp) {
  __shared__ __align__(16) float qs[32 * 68];
  __shared__ __align__(16) float ks[32 * 68];
  __shared__ __align__(16) float vs[32 * 64];
  __shared__ __align__(16) float attn[1056];   // 32*33; aliased for dw weights
  __shared__ float qsc[32], ksc[32];
  float* wsm = attn;  // 864 dw weights (read only before attn is written)

  const int tid = threadIdx.x, win = blockIdx.x, head = blockIdx.y;
  const int b = win >> 10, wy = (win >> 5) & 31, wx = win & 31;
  const int c = tid >> 3, i = tid & 7;
  const long long wbase = b * 65536 + (((long long)(wy * 8) + i) << 8) + wx * 8;

  // Stage 864 dw weights (strided; 864 > blockDim)
  for (int s = tid; s < 864; s += 256) {
    int c96 = s / 9, q = s - c96 * 9;
    int third = c96 >> 5, cw = c96 & 31;
    wsm[s] = dw_w[(third * 192 + head * 32 + cw) * 9 + q];
  }

  // Gather: thread (c,i) holds window row i (8 floats, 32B-aligned) of chan c
  float xa[8], xb[8];
  auto gather = [&](int t3, float* x) {
    const float* src =
        g_y + (long long)(t3 * 192 + head * 32 + c) * 262144 + wbase;
    float4 u = *(const float4*)src;
    float4 v = *(const float4*)(src + 4);
    x[0] = u.x; x[1] = u.y; x[2] = u.z; x[3] = u.w;
    x[4] = v.x; x[5] = v.y; x[6] = v.z; x[7] = v.w;
  };
  gather(0, xa);
  __syncthreads();  // wsm ready

  // Depthwise 3x3: vertical neighbors via shfl within octet, zero-padded
#pragma unroll
  for (int t3 = 0; t3 < 3; ++t3) {
    if (t3 < 2) gather(t3 + 1, xb);  // prefetch next third
    float pv[8], nx[8];
#pragma unroll
    for (int j = 0; j < 8; ++j) {
      pv[j] = __shfl_up_sync(0xffffffffu, xa[j], 1);
      nx[j] = __shfl_down_sync(0xffffffffu, xa[j], 1);
    }
    if (i == 0)
#pragma unroll
      for (int j = 0; j < 8; ++j) pv[j] = 0.f;
    if (i == 7)
#pragma unroll
      for (int j = 0; j < 8; ++j) nx[j] = 0.f;
    const float* wp = wsm + (t3 * 32 + c) * 9;
    float w0 = wp[0], w1 = wp[1], w2 = wp[2], w3 = wp[3], w4 = wp[4],
          w5 = wp[5], w6 = wp[6], w7 = wp[7], w8 = wp[8];
    float out[8];
#pragma unroll
    for (int j = 0; j < 8; ++j) {
      float s = w1 * pv[j] + w4 * xa[j] + w7 * nx[j];
      if (j > 0) s += w0 * pv[j - 1] + w3 * xa[j - 1] + w6 * nx[j - 1];
      if (j < 7) s += w2 * pv[j + 1] + w5 * xa[j + 1] + w8 * nx[j + 1];
      out[j] = s;
    }
    float* ob = (t3 == 0) ? qs : ((t3 == 1) ? ks : vs);
    int stride = (t3 == 2) ? 64 : 68;
    *(float4*)&ob[c * stride + i * 8] =
        make_float4(out[0], out[1], out[2], out[3]);
    *(float4*)&ob[c * stride + i * 8 + 4] =
        make_float4(out[4], out[5], out[6], out[7]);
    if (t3 < 2) {
#pragma unroll
      for (int j = 0; j < 8; ++j) xa[j] = xb[j];
    }
  }
  __syncthreads();

  // Row L2 norms: 8 lanes per row, two 16B chunks each (conflict-free)
  {
    float4 qa = *(const float4*)&qs[c * 68 + i * 4];
    float4 qb = *(const float4*)&qs[c * 68 + 32 + i * 4];
    float4 ka = *(const float4*)&ks[c * 68 + i * 4];
    float4 kb = *(const float4*)&ks[c * 68 + 32 + i * 4];
    float sq = qa.x * qa.x + qa.y * qa.y + qa.z * qa.z + qa.w * qa.w +
               qb.x * qb.x + qb.y * qb.y + qb.z * qb.z + qb.w * qb.w;
    float sk = ka.x * ka.x + ka.y * ka.y + ka.z * ka.z + ka.w * ka.w +
               kb.x * kb.x + kb.y * kb.y + kb.z * kb.z + kb.w * kb.w;
#pragma unroll
    for (int m = 1; m < 8; m <<= 1) {
      sq += __shfl_xor_sync(0xffffffffu, sq, m);
      sk += __shfl_xor_sync(0xffffffffu, sk, m);
    }
    if (i == 0) {
      qsc[c] = 1.f / fmaxf(sqrtf(sq), 1e-12f);
      ksc[c] = 1.f / fmaxf(sqrtf(sk), 1e-12f);
    }
  }
  __syncthreads();

  // Logits, 2x2 blocked: thread (rr,cc) -> rows {rr,rr+16} x cols {cc,cc+16}
  {
    const float tv = temp[head];
    int rr = tid >> 4, cc = tid & 15;
    const float* q0 = qs + rr * 68;
    const float* q1 = qs + (rr + 16) * 68;
    const float* k0 = ks + cc * 68;
    const float* k1 = ks + (cc + 16) * 68;
    float d00 = 0.f, d01 = 0.f, d10 = 0.f, d11 = 0.f;
#pragma unroll
    for (int k = 0; k < 64; k += 4) {
      float4 qa = *(const float4*)(q0 + k);
      float4 qb = *(const float4*)(q1 + k);
      float4 ka = *(const float4*)(k0 + k);
      float4 kb = *(const float4*)(k1 + k);
      d00 += qa.x * ka.x + qa.y * ka.y + qa.z * ka.z + qa.w * ka.w;
      d01 += qa.x * kb.x + qa.y * kb.y + qa.z * kb.z + qa.w * kb.w;
      d10 += qb.x * ka.x + qb.y * ka.y + qb.z * ka.z + qb.w * ka.w;
      d11 += qb.x * kb.x + qb.y * kb.y + qb.z * kb.z + qb.w * kb.w;
    }
    float s0 = qsc[rr] * tv, s1 = qsc[rr + 16] * tv;
    attn[rr * 33 + cc] = d00 * s0 * ksc[cc];
    attn[rr * 33 + cc + 16] = d01 * s0 * ksc[cc + 16];
    attn[(rr + 16) * 33 + cc] = d10 * s1 * ksc[cc];
    attn[(rr + 16) * 33 + cc + 16] = d11 * s1 * ksc[cc + 16];
  }
  __syncthreads();

  // Softmax: 8 lanes per row, 4 entries each
  {
    int r = tid >> 3, l = tid & 7;
    float v[4];
    float m = -1e30f;
#pragma unroll
    for (int q = 0; q < 4; ++q) {
      v[q] = attn[r * 33 + l + 8 * q];
      m = fmaxf(m, v[q]);
    }
#pragma unroll
    for (int mk = 1; mk < 8; mk <<= 1)
      m = fmaxf(m, __shfl_xor_sync(0xffffffffu, m, mk));
    float s = 0.f;
#pragma unroll
    for (int q = 0; q < 4; ++q) {
      v[q] = __expf(v[q] - m);
      s += v[q];
    }
#pragma unroll
    for (int mk = 1; mk < 8; mk <<= 1)
      s += __shfl_xor_sync(0xffffffffu, s, mk);
    float inv = 1.f / s;
#pragma unroll
    for (int q = 0; q < 4; ++q) attn[r * 33 + l + 8 * q] = v[q] * inv;
  }
  __syncthreads();

  // out = attn @ v, 2-row blocked; aligned scatter (rolled coords, no wrap)
  {
    int ro = tid >> 4, c4 = (tid & 15) * 4;
    float4 o0 = make_float4(0.f, 0.f, 0.f, 0.f);
    float4 o1 = make_float4(0.f, 0.f, 0.f, 0.f);
    const float* a0 = attn + ro * 33;
    const float* a1 = attn + (ro + 16) * 33;
#pragma unroll
    for (int cc = 0; cc < 32; ++cc) {
      float4 v4 = *(const float4*)&vs[cc * 64 + c4];
      float s0 = a0[cc], s1 = a1[cc];
      o0.x += s0 * v4.x; o0.y += s0 * v4.y; o0.z += s0 * v4.z; o0.w += s0 * v4.w;
      o1.x += s1 * v4.x; o1.y += s1 * v4.y; o1.z += s1 * v4.z; o1.w += s1 * v4.w;
    }
    int i0 = c4 >> 3, j0 = c4 & 7;  // j0 in {0,4}
    long long boff =
        b * 65536 + (((long long)(wy * 8) + i0) << 8) + wx * 8 + j0;
    *(float4*)(g_att + (long long)(head * 32 + ro) * 262144 + boff) = o0;
    *(float4*)(g_att + (long long)(head * 32 + ro + 16) * 262144 + boff) = o1;
  }
}

// ---------------------------------------------------------------------------
extern "C" void kernel_launch(void* const* d_in, const int* in_sizes, int n_in,
                              void* d_out, int out_size) {
  const float *x = nullptr, *qkvw = nullptr, *dww = nullptr, *projw = nullptr,
              *temp = nullptr;
  for (int i = 0; i < n_in; ++i) {
    switch (in_sizes[i]) {
      case 50331648: x = (const float*)d_in[i]; break;      // 4*192*256*256
      case 110592:   qkvw = (const float*)d_in[i]; break;   // 576*192
      case 5184:     dww = (const float*)d_in[i]; break;    // 576*9
      case 36864:    projw = (const float*)d_in[i]; break;  // 192*192
      case 6:        temp = (const float*)d_in[i]; break;   // heads
    }
  }

  float* gy;  cudaGetSymbolAddress((void**)&gy, g_y);
  float* ga;  cudaGetSymbolAddress((void**)&ga, g_att);

  // GEMM1: g_y(rolled)[576, (b,pos)] = qkv_w @ x   (roll = -4 mod 256)
  gemm_mma<<<dim3(2048, 5), 256>>>(qkvw, x, gy, 576, 65536LL, 12582912LL,
                                   262144LL, 65536LL, 252);
  // dwconv + channel attention per (window, head), rolled coords throughout
  k2_dw_attn<<<dim3(4096, 6), 256>>>(dww, temp);
  // GEMM2: d_out(natural) = proj_w @ g_att(rolled)  (roll = +4)
  gemm_mma<<<dim3(2048, 2), 256>>>(projw, ga, (float*)d_out, 192, 262144LL,
                                   65536LL, 65536LL, 12582912LL, 4);
}

// round 16
// speedup vs baseline: 1.0383x; 1.0383x over previous
#include <cuda_runtime.h>
#include <cstdint>

// Scratch (module-scope device globals; no runtime allocation)
// g_y and g_att are stored in ROLLED coordinates: R(h,w) = natural(h+4, w+4).
__device__ float g_y[576LL * 262144];    // qkv-linear output, [o][b][pos_rolled]
__device__ float g_att[192LL * 262144];  // attention output,  [c][b][pos_rolled]
__device__ float g_wq[110592];           // qkv_w pre-converted to tf32 bits
__device__ float g_wp[36864];            // proj_w pre-converted to tf32 bits

// ---------------------------------------------------------------------------
__device__ __forceinline__ uint32_t smem_u32(const void* p) {
  uint32_t a;
  asm("{ .reg .u64 t; cvta.to.shared.u64 t, %1; cvt.u32.u64 %0, t; }"
      : "=r"(a) : "l"(p));
  return a;
}
#define CPA16(dst, src, sz) \
  asm volatile("cp.async.cg.shared.global [%0], [%1], 16, %2;" ::"r"(dst), "l"(src), "r"(sz))
#define CPA_COMMIT() asm volatile("cp.async.commit_group;")
#define CPA_WAIT(n) asm volatile("cp.async.wait_group %0;" ::"n"(n) : "memory")

__device__ __forceinline__ uint32_t f2tf(float f) {
  uint32_t u;
  asm("cvt.rna.tf32.f32 %0, %1;" : "=r"(u) : "f"(f));
  return u;
}
__device__ __forceinline__ void mma8(float* d, const uint32_t* a,
                                     const uint32_t* b) {
  asm volatile(
      "mma.sync.aligned.m16n8k8.row.col.f32.tf32.tf32.f32 "
      "{%0,%1,%2,%3},{%4,%5,%6,%7},{%8,%9},{%0,%1,%2,%3};"
      : "+f"(d[0]), "+f"(d[1]), "+f"(d[2]), "+f"(d[3])
      : "r"(a[0]), "r"(a[1]), "r"(a[2]), "r"(a[3]), "r"(b[0]), "r"(b[1]));
}

// Pre-convert weights to tf32 bit patterns (one tiny launch per call)
__global__ void conv_weights(const float* __restrict__ qkvw,
                             const float* __restrict__ projw) {
  int i = blockIdx.x * 256 + threadIdx.x;
  if (i < 110592) g_wq[i] = __uint_as_float(f2tf(qkvw[i]));
  if (i < 36864) g_wp[i] = __uint_as_float(f2tf(projw[i]));
}

// ---------------------------------------------------------------------------
// Out[m, pos_out] = sum_k W[m,k] * In[k, pos_out + roll]   (roll mod 256 per
// axis, applied on the LOAD side: every B tile covers one h row, the shift is
// 16B-granular, so rolled chunk loads stay aligned and never straddle a wrap).
// W holds pre-converted tf32 bits. CTA tile 128x128, K=192, double-buffered.
// ---------------------------------------------------------------------------
__global__ void __launch_bounds__(256, 2) gemm_mma(
    const float* __restrict__ W, const float* __restrict__ In,
    float* __restrict__ Out, int Mvalid, long long ch_str, long long b_str,
    long long o_str, long long ob_str, int roll) {
  __shared__ __align__(16) float As[2][128 * 20];
  __shared__ __align__(16) float Bs[2][16 * 136];

  const int tid = threadIdx.x;
  const int warp = tid >> 5, lane = tid & 31, gid = lane >> 2, tig = lane & 3;
  const int wm = warp & 1, wn = warp >> 1;
  const int m0 = blockIdx.y << 7;
  const int n0 = blockIdx.x << 7;
  const int bb = n0 >> 16, pos0 = n0 & 65535;
  const int h = pos0 >> 8, w0 = pos0 & 255;
  const int hs = (h + roll) & 255;  // rolled source row (constant per tile)
  const float* inb = In + bb * b_str + ((long long)hs << 8);
  const uint32_t sA = smem_u32(As), sB = smem_u32(Bs);

  float acc[4][4][4];
#pragma unroll
  for (int i = 0; i < 4; ++i)
#pragma unroll
    for (int j = 0; j < 4; ++j)
#pragma unroll
      for (int q = 0; q < 4; ++q) acc[i][j][q] = 0.f;

  auto loadA = [&](int buf, int kc) {
#pragma unroll
    for (int t = 0; t < 2; ++t) {
      int idx = (t << 8) + tid;
      int r = idx >> 2, q = idx & 3;
      int m = m0 + r;
      int valid = m < Mvalid;
      const float* src = W + (long long)(valid ? m : 0) * 192 + kc + (q << 2);
      uint32_t dst = sA + (uint32_t)(buf * 2560 + r * 20 + q * 4) * 4;
      CPA16(dst, src, valid ? 16 : 0);
    }
  };
  auto loadB = [&](int buf, int kc) {
#pragma unroll
    for (int t = 0; t < 2; ++t) {
      int idx = (t << 8) + tid;
      int r = idx >> 5, q = idx & 31;
      int ws = (w0 + (q << 2) + roll) & 255;  // rolled source col, 16B aligned
      const float* src = inb + (long long)(kc + r) * ch_str + ws;
      uint32_t dst = sB + (uint32_t)(buf * 2176 + r * 136 + q * 4) * 4;
      CPA16(dst, src, 16);
    }
  };

  auto compute = [&](int buf) {
    const float* A = As[buf];
    const float* B = Bs[buf];
#pragma unroll
    for (int kb = 0; kb < 2; ++kb) {
      const int kk = kb * 8;
      uint32_t af[4][4];
#pragma unroll
      for (int mf = 0; mf < 4; ++mf) {
        const float* ap = A + (wm * 64 + mf * 16 + gid) * 20 + kk + tig;
        af[mf][0] = __float_as_uint(ap[0]);     // already tf32 bits
        af[mf][1] = __float_as_uint(ap[160]);
        af[mf][2] = __float_as_uint(ap[4]);
        af[mf][3] = __float_as_uint(ap[164]);
      }
      uint32_t bf[4][2];
#pragma unroll
      for (int nf = 0; nf < 4; ++nf) {
        const float* bp = B + (kk + tig) * 136 + wn * 32 + nf * 8 + gid;
        bf[nf][0] = f2tf(bp[0]);
        bf[nf][1] = f2tf(bp[544]);
      }
#pragma unroll
      for (int mf = 0; mf < 4; ++mf)
#pragma unroll
        for (int nf = 0; nf < 4; ++nf) mma8(acc[mf][nf], af[mf], bf[nf]);
    }
  };

  loadA(0, 0);
  loadB(0, 0);
  CPA_COMMIT();
#pragma unroll 1
  for (int i = 0; i < 12; ++i) {
    if (i + 1 < 12) {
      loadA((i + 1) & 1, (i + 1) * 16);
      loadB((i + 1) & 1, (i + 1) * 16);
      CPA_COMMIT();
      CPA_WAIT(1);
    } else {
      CPA_WAIT(0);
    }
    __syncthreads();
    compute(i & 1);
    __syncthreads();
  }

  // Epilogue: sequential float2 stores (no roll on the store side)
#pragma unroll
  for (int mf = 0; mf < 4; ++mf) {
    int mA = m0 + wm * 64 + mf * 16 + gid;
    int mB = mA + 8;
#pragma unroll
    for (int nf = 0; nf < 4; ++nf) {
      int c = pos0 + wn * 32 + nf * 8 + 2 * tig;
      if (mA < Mvalid)
        *(float2*)(Out + (long long)mA * o_str + bb * ob_str + c) =
            make_float2(acc[mf][nf][0], acc[mf][nf][1]);
      if (mB < Mvalid)
        *(float2*)(Out + (long long)mB * o_str + bb * ob_str + c) =
            make_float2(acc[mf][nf][2], acc[mf][nf][3]);
    }
  }
}

// ---------------------------------------------------------------------------
// k2: per (window, head). g_y / g_att in rolled coords -> 32B-aligned,
// branch-free window access. All 3 thirds gathered up-front (MLP=6), depthwise
// 3x3 via warp shuffles, L2-norm channel attention (2x2 blocking), aligned
// scatter.
// ---------------------------------------------------------------------------
__global__ void __launch_bounds__(256) k2_dw_attn(
    const float* __restrict__ dw_w, const float* __restrict__ temp) {
  __shared__ __align__(16) float qs[32 * 68];
  __shared__ __align__(16) float ks[32 * 68];
  __shared__ __align__(16) float vs[32 * 64];
  __shared__ __align__(16) float attn[1056];   // 32*33; aliased for dw weights
  __shared__ float qsc[32], ksc[32];
  float* wsm = attn;  // 864 dw weights (read only before attn is written)

  const int tid = threadIdx.x, win = blockIdx.x, head = blockIdx.y;
  const int b = win >> 10, wy = (win >> 5) & 31, wx = win & 31;
  const int c = tid >> 3, i = tid & 7;
  const long long wbase = b * 65536 + (((long long)(wy * 8) + i) << 8) + wx * 8;

  // Stage 864 dw weights (strided; 864 > blockDim)
  for (int s = tid; s < 864; s += 256) {
    int c96 = s / 9, q = s - c96 * 9;
    int third = c96 >> 5, cw = c96 & 31;
    wsm[s] = dw_w[(third * 192 + head * 32 + cw) * 9 + q];
  }

  // Gather all 3 thirds up-front: 6 float4 loads in flight per thread
  float xr[3][8];
#pragma unroll
  for (int t3 = 0; t3 < 3; ++t3) {
    const float* src =
        g_y + (long long)(t3 * 192 + head * 32 + c) * 262144 + wbase;
    float4 u = *(const float4*)src;
    float4 v = *(const float4*)(src + 4);
    xr[t3][0] = u.x; xr[t3][1] = u.y; xr[t3][2] = u.z; xr[t3][3] = u.w;
    xr[t3][4] = v.x; xr[t3][5] = v.y; xr[t3][6] = v.z; xr[t3][7] = v.w;
  }
  __syncthreads();  // wsm ready

  // Depthwise 3x3: vertical neighbors via shfl within octet, zero-padded
#pragma unroll
  for (int t3 = 0; t3 < 3; ++t3) {
    float* xa = xr[t3];
    float pv[8], nx[8];
#pragma unroll
    for (int j = 0; j < 8; ++j) {
      pv[j] = __shfl_up_sync(0xffffffffu, xa[j], 1);
      nx[j] = __shfl_down_sync(0xffffffffu, xa[j], 1);
    }
    if (i == 0)
#pragma unroll
      for (int j = 0; j < 8; ++j) pv[j] = 0.f;
    if (i == 7)
#pragma unroll
      for (int j = 0; j < 8; ++j) nx[j] = 0.f;
    const float* wp = wsm + (t3 * 32 + c) * 9;
    float w0 = wp[0], w1 = wp[1], w2 = wp[2], w3 = wp[3], w4 = wp[4],
          w5 = wp[5], w6 = wp[6], w7 = wp[7], w8 = wp[8];
    float out[8];
#pragma unroll
    for (int j = 0; j < 8; ++j) {
      float s = w1 * pv[j] + w4 * xa[j] + w7 * nx[j];
      if (j > 0) s += w0 * pv[j - 1] + w3 * xa[j - 1] + w6 * nx[j - 1];
      if (j < 7) s += w2 * pv[j + 1] + w5 * xa[j + 1] + w8 * nx[j + 1];
      out[j] = s;
    }
    float* ob = (t3 == 0) ? qs : ((t3 == 1) ? ks : vs);
    int stride = (t3 == 2) ? 64 : 68;
    *(float4*)&ob[c * stride + i * 8] =
        make_float4(out[0], out[1], out[2], out[3]);
    *(float4*)&ob[c * stride + i * 8 + 4] =
        make_float4(out[4], out[5], out[6], out[7]);
  }
  __syncthreads();

  // Row L2 norms: 8 lanes per row, two 16B chunks each (conflict-free)
  {
    float4 qa = *(const float4*)&qs[c * 68 + i * 4];
    float4 qb = *(const float4*)&qs[c * 68 + 32 + i * 4];
    float4 ka = *(const float4*)&ks[c * 68 + i * 4];
    float4 kb = *(const float4*)&ks[c * 68 + 32 + i * 4];
    float sq = qa.x * qa.x + qa.y * qa.y + qa.z * qa.z + qa.w * qa.w +
               qb.x * qb.x + qb.y * qb.y + qb.z * qb.z + qb.w * qb.w;
    float sk = ka.x * ka.x + ka.y * ka.y + ka.z * ka.z + ka.w * ka.w +
               kb.x * kb.x + kb.y * kb.y + kb.z * kb.z + kb.w * kb.w;
#pragma unroll
    for (int m = 1; m < 8; m <<= 1) {
      sq += __shfl_xor_sync(0xffffffffu, sq, m);
      sk += __shfl_xor_sync(0xffffffffu, sk, m);
    }
    if (i == 0) {
      qsc[c] = 1.f / fmaxf(sqrtf(sq), 1e-12f);
      ksc[c] = 1.f / fmaxf(sqrtf(sk), 1e-12f);
    }
  }
  __syncthreads();

  // Logits, 2x2 blocked: thread (rr,cc) -> rows {rr,rr+16} x cols {cc,cc+16}
  {
    const float tv = temp[head];
    int rr = tid >> 4, cc = tid & 15;
    const float* q0 = qs + rr * 68;
    const float* q1 = qs + (rr + 16) * 68;
    const float* k0 = ks + cc * 68;
    const float* k1 = ks + (cc + 16) * 68;
    float d00 = 0.f, d01 = 0.f, d10 = 0.f, d11 = 0.f;
#pragma unroll
    for (int k = 0; k < 64; k += 4) {
      float4 qa = *(const float4*)(q0 + k);
      float4 qb = *(const float4*)(q1 + k);
      float4 ka = *(const float4*)(k0 + k);
      float4 kb = *(const float4*)(k1 + k);
      d00 += qa.x * ka.x + qa.y * ka.y + qa.z * ka.z + qa.w * ka.w;
      d01 += qa.x * kb.x + qa.y * kb.y + qa.z * kb.z + qa.w * kb.w;
      d10 += qb.x * ka.x + qb.y * ka.y + qb.z * ka.z + qb.w * ka.w;
      d11 += qb.x * kb.x + qb.y * kb.y + qb.z * kb.z + qb.w * kb.w;
    }
    float s0 = qsc[rr] * tv, s1 = qsc[rr + 16] * tv;
    attn[rr * 33 + cc] = d00 * s0 * ksc[cc];
    attn[rr * 33 + cc + 16] = d01 * s0 * ksc[cc + 16];
    attn[(rr + 16) * 33 + cc] = d10 * s1 * ksc[cc];
    attn[(rr + 16) * 33 + cc + 16] = d11 * s1 * ksc[cc + 16];
  }
  __syncthreads();

  // Softmax: 8 lanes per row, 4 entries each
  {
    int r = tid >> 3, l = tid & 7;
    float v[4];
    float m = -1e30f;
#pragma unroll
    for (int q = 0; q < 4; ++q) {
      v[q] = attn[r * 33 + l + 8 * q];
      m = fmaxf(m, v[q]);
    }
#pragma unroll
    for (int mk = 1; mk < 8; mk <<= 1)
      m = fmaxf(m, __shfl_xor_sync(0xffffffffu, m, mk));
    float s = 0.f;
#pragma unroll
    for (int q = 0; q < 4; ++q) {
      v[q] = __expf(v[q] - m);
      s += v[q];
    }
#pragma unroll
    for (int mk = 1; mk < 8; mk <<= 1)
      s += __shfl_xor_sync(0xffffffffu, s, mk);
    float inv = 1.f / s;
#pragma unroll
    for (int q = 0; q < 4; ++q) attn[r * 33 + l + 8 * q] = v[q] * inv;
  }
  __syncthreads();

  // out = attn @ v, 2-row blocked; aligned scatter (rolled coords, no wrap)
  {
    int ro = tid >> 4, c4 = (tid & 15) * 4;
    float4 o0 = make_float4(0.f, 0.f, 0.f, 0.f);
    float4 o1 = make_float4(0.f, 0.f, 0.f, 0.f);
    const float* a0 = attn + ro * 33;
    const float* a1 = attn + (ro + 16) * 33;
#pragma unroll
    for (int cc = 0; cc < 32; ++cc) {
      float4 v4 = *(const float4*)&vs[cc * 64 + c4];
      float s0 = a0[cc], s1 = a1[cc];
      o0.x += s0 * v4.x; o0.y += s0 * v4.y; o0.z += s0 * v4.z; o0.w += s0 * v4.w;
      o1.x += s1 * v4.x; o1.y += s1 * v4.y; o1.z += s1 * v4.z; o1.w += s1 * v4.w;
    }
    int i0 = c4 >> 3, j0 = c4 & 7;  // j0 in {0,4}
    long long boff =
        b * 65536 + (((long long)(wy * 8) + i0) << 8) + wx * 8 + j0;
    *(float4*)(g_att + (long long)(head * 32 + ro) * 262144 + boff) = o0;
    *(float4*)(g_att + (long long)(head * 32 + ro + 16) * 262144 + boff) = o1;
  }
}

// ---------------------------------------------------------------------------
extern "C" void kernel_launch(void* const* d_in, const int* in_sizes, int n_in,
                              void* d_out, int out_size) {
  const float *x = nullptr, *qkvw = nullptr, *dww = nullptr, *projw = nullptr,
              *temp = nullptr;
  for (int i = 0; i < n_in; ++i) {
    switch (in_sizes[i]) {
      case 50331648: x = (const float*)d_in[i]; break;      // 4*192*256*256
      case 110592:   qkvw = (const float*)d_in[i]; break;   // 576*192
      case 5184:     dww = (const float*)d_in[i]; break;    // 576*9
      case 36864:    projw = (const float*)d_in[i]; break;  // 192*192
      case 6:        temp = (const float*)d_in[i]; break;   // heads
    }
  }

  float* gy;   cudaGetSymbolAddress((void**)&gy, g_y);
  float* ga;   cudaGetSymbolAddress((void**)&ga, g_att);
  float* gwq;  cudaGetSymbolAddress((void**)&gwq, g_wq);
  float* gwp;  cudaGetSymbolAddress((void**)&gwp, g_wp);

  // Pre-convert weights to tf32 bits (~3us)
  conv_weights<<<432, 256>>>(qkvw, projw);

  // GEMM1: g_y(rolled) = qkv_w @ x, roll=+4 applied on x loads
  gemm_mma<<<dim3(2048, 5), 256>>>(gwq, x, gy, 576, 65536LL, 12582912LL,
                                   262144LL, 65536LL, 4);
  // dwconv + channel attention per (window, head), rolled coords throughout
  k2_dw_attn<<<dim3(4096, 6), 256>>>(dww, temp);
  // GEMM2: d_out(natural) = proj_w @ g_att(rolled), roll=-4 on g_att loads
  gemm_mma<<<dim3(2048, 2), 256>>>(gwp, ga, (float*)d_out, 192, 262144LL,
                                   65536LL, 65536LL, 12582912LL, 252);
}